// round 7
// baseline (speedup 1.0000x reference)
#include <cuda_runtime.h>

// Problem constants (B=1, N=4, C=16, D=64, H=128, W=128)
#define NCTX 4
#define CH   16
#define VOX  (64 * 128 * 128)   // 1,048,576 voxels
#define VPT  2                  // voxels per thread (float2)
#define TPB  256
#define NSM  148
#define CTAS_PER_SM 5
#define GRID (NSM * CTAS_PER_SM)           // 740 persistent CTAs
#define NTILES (VOX / (TPB * VPT))         // 2048 voxel tiles

__global__ __launch_bounds__(TPB, CTAS_PER_SM) void volattn3d_kernel(
    const float* __restrict__ q,      // [C][V]
    const float* __restrict__ k,      // [N][C][V]
    const float* __restrict__ v,      // [N][C][V]
    const float* __restrict__ w_proj, // [C][C]
    const float* __restrict__ b_proj, // [C]
    float* __restrict__ out)          // [C][V]
{
    // swT[c*16 + o] = w[o][c]  (transposed, so phase C reads float4 runs of o)
    __shared__ __align__(16) float swT[CH * CH];
    __shared__ float sb[CH];
    // per-thread x accumulator spill area: sx[c][tid], thread-private columns
    __shared__ float2 sx[CH * TPB];   // 32 KB

    {
        int t = threadIdx.x;
        if (t < CH * CH) swT[t] = w_proj[(t % CH) * CH + (t / CH)];
        if (t < CH)      sb[t]  = b_proj[t];
    }
    __syncthreads();

    const int tid = threadIdx.x;

    for (int tile = blockIdx.x; tile < NTILES; tile += GRID) {
        const int p = (tile * TPB + tid) * VPT;   // base voxel pair
        const float* qp = q + p;
        const float* kp = k + p;
        const float* vp = v + p;

        // ---- phase A: scores[n] = (q . k_n) ----
        float2 sc[NCTX];
#pragma unroll
        for (int n = 0; n < NCTX; ++n) sc[n] = make_float2(0.f, 0.f);

#pragma unroll
        for (int c = 0; c < CH; ++c) {
            const float2 qv = __ldcs(reinterpret_cast<const float2*>(qp + c * VOX));
#pragma unroll
            for (int n = 0; n < NCTX; ++n) {
                const float2 kv = __ldcs(reinterpret_cast<const float2*>(kp + (n * CH + c) * VOX));
                sc[n].x = fmaf(qv.x, kv.x, sc[n].x);
                sc[n].y = fmaf(qv.y, kv.y, sc[n].y);
            }
        }
#pragma unroll
        for (int n = 0; n < NCTX; ++n) { sc[n].x *= 0.25f; sc[n].y *= 0.25f; }

        // ---- softmax over n ----
        float2 mx = sc[0];
#pragma unroll
        for (int n = 1; n < NCTX; ++n) {
            mx.x = fmaxf(mx.x, sc[n].x);
            mx.y = fmaxf(mx.y, sc[n].y);
        }
        float2 ssum = make_float2(0.f, 0.f);
#pragma unroll
        for (int n = 0; n < NCTX; ++n) {
            sc[n].x = __expf(sc[n].x - mx.x);
            sc[n].y = __expf(sc[n].y - mx.y);
            ssum.x += sc[n].x;
            ssum.y += sc[n].y;
        }
        const float2 rs = make_float2(__frcp_rn(ssum.x), __frcp_rn(ssum.y));
#pragma unroll
        for (int n = 0; n < NCTX; ++n) { sc[n].x *= rs.x; sc[n].y *= rs.y; }

        // ---- phase B: x[c] = sum_n attn[n] * v[n][c], accumulate into smem ----
#pragma unroll
        for (int c = 0; c < CH; ++c) {
            float2 a = make_float2(0.f, 0.f);
#pragma unroll
            for (int n = 0; n < NCTX; ++n) {
                const float2 vv = __ldcs(reinterpret_cast<const float2*>(vp + (n * CH + c) * VOX));
                a.x = fmaf(sc[n].x, vv.x, a.x);
                a.y = fmaf(sc[n].y, vv.y, a.y);
            }
            sx[c * TPB + tid] = a;   // thread-private, conflict-free
        }

        // ---- phase C: out[o] = sum_c w[o][c] * x[c] + b[o], 4 outputs at a time ----
        float* op = out + p;
#pragma unroll
        for (int oc = 0; oc < CH / 4; ++oc) {
            float2 po[4];
#pragma unroll
            for (int j = 0; j < 4; ++j) {
                const float bo = sb[oc * 4 + j];
                po[j] = make_float2(bo, bo);
            }
#pragma unroll
            for (int c = 0; c < CH; ++c) {
                const float2 xv = sx[c * TPB + tid];
                const float4 wv = *reinterpret_cast<const float4*>(&swT[c * CH + oc * 4]);
                po[0].x = fmaf(wv.x, xv.x, po[0].x); po[0].y = fmaf(wv.x, xv.y, po[0].y);
                po[1].x = fmaf(wv.y, xv.x, po[1].x); po[1].y = fmaf(wv.y, xv.y, po[1].y);
                po[2].x = fmaf(wv.z, xv.x, po[2].x); po[2].y = fmaf(wv.z, xv.y, po[2].y);
                po[3].x = fmaf(wv.w, xv.x, po[3].x); po[3].y = fmaf(wv.w, xv.y, po[3].y);
            }
#pragma unroll
            for (int j = 0; j < 4; ++j)
                __stcs(reinterpret_cast<float2*>(op + (oc * 4 + j) * VOX), po[j]);
        }
    }
}

extern "C" void kernel_launch(void* const* d_in, const int* in_sizes, int n_in,
                              void* d_out, int out_size) {
    const float* q      = (const float*)d_in[0];
    const float* k      = (const float*)d_in[1];
    const float* v      = (const float*)d_in[2];
    const float* w_proj = (const float*)d_in[3];
    const float* b_proj = (const float*)d_in[4];
    float* out = (float*)d_out;

    volattn3d_kernel<<<GRID, TPB>>>(q, k, v, w_proj, b_proj, out);
}

// round 8
// speedup vs baseline: 1.2074x; 1.2074x over previous
#include <cuda_runtime.h>

// Problem constants (B=1, N=4, C=16, D=64, H=128, W=128)
#define NCTX 4
#define CH   16
#define VOX  (64 * 128 * 128)   // 1,048,576 voxels
#define VPT  2                  // voxels per thread, main phase (float2)
#define TPB  256
#define NSM  148
#define CTAS_PER_SM 4
#define GRID (NSM * CTAS_PER_SM)            // 592 persistent CTAs
#define TILE_VOX (TPB * VPT)                // 512 voxels per tile
#define NTILES (VOX / TILE_VOX)             // 2048
#define FULL_TPC 3                          // balanced full tiles per CTA
#define FULL_TILES (GRID * FULL_TPC)        // 1776
#define REM_BASE (FULL_TILES * TILE_VOX)    // 909,312
#define REM_VOX (VOX - REM_BASE)            // 139,264

__global__ __launch_bounds__(TPB, CTAS_PER_SM) void volattn3d_kernel(
    const float* __restrict__ q,      // [C][V]
    const float* __restrict__ k,      // [N][C][V]
    const float* __restrict__ v,      // [N][C][V]
    const float* __restrict__ w_proj, // [C][C]
    const float* __restrict__ b_proj, // [C]
    float* __restrict__ out)          // [C][V]
{
    __shared__ float sw[CH * CH];
    __shared__ float sb[CH];
    {
        int t = threadIdx.x;
        if (t < CH * CH) sw[t] = w_proj[t];
        if (t < CH)      sb[t] = b_proj[t];
    }
    __syncthreads();

    const int tid = threadIdx.x;

    // ================= Phase 1: 3 full float2 tiles per CTA (balanced) ======
#pragma unroll 1
    for (int it = 0; it < FULL_TPC; ++it) {
        const int tile = blockIdx.x * FULL_TPC + it;
        const int p = (tile * TPB + tid) * VPT;
        const float* qp = q + p;
        const float* kp = k + p;
        const float* vp = v + p;

        float2 sc[NCTX];
#pragma unroll
        for (int n = 0; n < NCTX; ++n) sc[n] = make_float2(0.f, 0.f);

#pragma unroll
        for (int c = 0; c < CH; ++c) {
            const float2 qv = __ldcs(reinterpret_cast<const float2*>(qp + c * VOX));
#pragma unroll
            for (int n = 0; n < NCTX; ++n) {
                const float2 kv = __ldcs(reinterpret_cast<const float2*>(kp + (n * CH + c) * VOX));
                sc[n].x = fmaf(qv.x, kv.x, sc[n].x);
                sc[n].y = fmaf(qv.y, kv.y, sc[n].y);
            }
        }
#pragma unroll
        for (int n = 0; n < NCTX; ++n) { sc[n].x *= 0.25f; sc[n].y *= 0.25f; }

        float2 mx = sc[0];
#pragma unroll
        for (int n = 1; n < NCTX; ++n) {
            mx.x = fmaxf(mx.x, sc[n].x);
            mx.y = fmaxf(mx.y, sc[n].y);
        }
        float2 ssum = make_float2(0.f, 0.f);
#pragma unroll
        for (int n = 0; n < NCTX; ++n) {
            sc[n].x = __expf(sc[n].x - mx.x);
            sc[n].y = __expf(sc[n].y - mx.y);
            ssum.x += sc[n].x;
            ssum.y += sc[n].y;
        }
        const float2 rs = make_float2(__frcp_rn(ssum.x), __frcp_rn(ssum.y));
#pragma unroll
        for (int n = 0; n < NCTX; ++n) { sc[n].x *= rs.x; sc[n].y *= rs.y; }

        float2 x[CH];
#pragma unroll
        for (int c = 0; c < CH; ++c) x[c] = make_float2(0.f, 0.f);
#pragma unroll
        for (int n = 0; n < NCTX; ++n) {
#pragma unroll
            for (int c = 0; c < CH; ++c) {
                const float2 vv = __ldcs(reinterpret_cast<const float2*>(vp + (n * CH + c) * VOX));
                x[c].x = fmaf(sc[n].x, vv.x, x[c].x);
                x[c].y = fmaf(sc[n].y, vv.y, x[c].y);
            }
        }

        float* op = out + p;
#pragma unroll
        for (int o = 0; o < CH; ++o) {
            const float bo = sb[o];
            float2 acc = make_float2(bo, bo);
#pragma unroll
            for (int c = 0; c < CH; ++c) {
                const float wv = sw[o * CH + c];
                acc.x = fmaf(wv, x[c].x, acc.x);
                acc.y = fmaf(wv, x[c].y, acc.y);
            }
            __stcs(reinterpret_cast<float2*>(op + o * VOX), acc);
        }
    }

    // ============ Phase 2: remainder, 1 scalar voxel per thread (balanced) ==
    {
        const int g = blockIdx.x * TPB + tid;     // 0 .. 151551
        if (g < REM_VOX) {
            const int p = REM_BASE + g;
            const float* qp = q + p;
            const float* kp = k + p;
            const float* vp = v + p;

            float sc0 = 0.f, sc1 = 0.f, sc2 = 0.f, sc3 = 0.f;
#pragma unroll
            for (int c = 0; c < CH; ++c) {
                const float qv = __ldcs(qp + c * VOX);
                sc0 = fmaf(qv, __ldcs(kp + (0 * CH + c) * VOX), sc0);
                sc1 = fmaf(qv, __ldcs(kp + (1 * CH + c) * VOX), sc1);
                sc2 = fmaf(qv, __ldcs(kp + (2 * CH + c) * VOX), sc2);
                sc3 = fmaf(qv, __ldcs(kp + (3 * CH + c) * VOX), sc3);
            }
            sc0 *= 0.25f; sc1 *= 0.25f; sc2 *= 0.25f; sc3 *= 0.25f;

            const float mx = fmaxf(fmaxf(sc0, sc1), fmaxf(sc2, sc3));
            sc0 = __expf(sc0 - mx);
            sc1 = __expf(sc1 - mx);
            sc2 = __expf(sc2 - mx);
            sc3 = __expf(sc3 - mx);
            const float rs = __frcp_rn(sc0 + sc1 + sc2 + sc3);
            sc0 *= rs; sc1 *= rs; sc2 *= rs; sc3 *= rs;

            float x[CH];
#pragma unroll
            for (int c = 0; c < CH; ++c) {
                float a = sc0 * __ldcs(vp + (0 * CH + c) * VOX);
                a = fmaf(sc1, __ldcs(vp + (1 * CH + c) * VOX), a);
                a = fmaf(sc2, __ldcs(vp + (2 * CH + c) * VOX), a);
                a = fmaf(sc3, __ldcs(vp + (3 * CH + c) * VOX), a);
                x[c] = a;
            }

            float* op = out + p;
#pragma unroll
            for (int o = 0; o < CH; ++o) {
                float acc = sb[o];
#pragma unroll
                for (int c = 0; c < CH; ++c)
                    acc = fmaf(sw[o * CH + c], x[c], acc);
                __stcs(op + o * VOX, acc);
            }
        }
    }
}

extern "C" void kernel_launch(void* const* d_in, const int* in_sizes, int n_in,
                              void* d_out, int out_size) {
    const float* q      = (const float*)d_in[0];
    const float* k      = (const float*)d_in[1];
    const float* v      = (const float*)d_in[2];
    const float* w_proj = (const float*)d_in[3];
    const float* b_proj = (const float*)d_in[4];
    float* out = (float*)d_out;

    volattn3d_kernel<<<GRID, TPB>>>(q, k, v, w_proj, b_proj, out);
}